// round 15
// baseline (speedup 1.0000x reference)
#include <cuda_runtime.h>
#include <cuda_fp16.h>
#include <cuda_bf16.h>
#include <math.h>
#include <stdint.h>

// ---------------------------------------------------------------------------
// Neural CA step, fp16 mma.sync (m16n8k16), fp32 accumulate.
//   Pack:   one-time weight fragment packing (w0 reorder + sobel fold).
//   Pass A: TWO 8x32 tiles per block (grid 2048), software-pipelined:
//           tile1 halo cp.async'd (fp32 staging in the dead Y region) under
//           tile0 MMA/epilogue. Halo as half2 planes; weights via cp.async.
//           x_new direct to out; alphas as bf16x2.
//   Pass B: fix-up — 2 px/thread shared vertical maxes; zero dead pixels.
// ---------------------------------------------------------------------------

#define CH    16
#define NK    48
#define HID   128
#define IMG   256
#define BATCH 16

__device__ uint32_t g_aon[(size_t)BATCH * IMG * IMG];  // bf16x2 (alpha_old, alpha_new)
__device__ uint2 g_w0f[3 * 8 * 32 * 2];   // uint4-pairable GEMM1 B-frags
__device__ uint2 g_w1f[8 * 32 * 2];       // uint4-pairable GEMM2 B-frags

__device__ __forceinline__ uint32_t pk2h(float lo, float hi) {
    __half2 h = __floats2half2_rn(lo, hi);
    return *(uint32_t*)&h;
}
__device__ __forceinline__ uint32_t pk2bf(float lo, float hi) {
    __nv_bfloat162 h = __floats2bfloat162_rn(lo, hi);
    return *(uint32_t*)&h;
}
__device__ __forceinline__ uint32_t hadd2u(uint32_t a, uint32_t b) {
    uint32_t r; asm("add.f16x2 %0, %1, %2;" : "=r"(r) : "r"(a), "r"(b)); return r;
}
__device__ __forceinline__ uint32_t hsub2u(uint32_t a, uint32_t b) {
    uint32_t r; asm("sub.f16x2 %0, %1, %2;" : "=r"(r) : "r"(a), "r"(b)); return r;
}
__device__ __forceinline__ __nv_bfloat162 bmax2(__nv_bfloat162 a, __nv_bfloat162 b) {
    return __hmax2(a, b);
}

__device__ __forceinline__ void mma_f16(float c[4],
                                        uint32_t a0, uint32_t a1, uint32_t a2, uint32_t a3,
                                        uint32_t b0, uint32_t b1) {
    asm volatile(
        "mma.sync.aligned.m16n8k16.row.col.f32.f16.f16.f32 "
        "{%0,%1,%2,%3}, {%4,%5,%6,%7}, {%8,%9}, {%0,%1,%2,%3};"
        : "+f"(c[0]), "+f"(c[1]), "+f"(c[2]), "+f"(c[3])
        : "r"(a0), "r"(a1), "r"(a2), "r"(a3), "r"(b0), "r"(b1));
}

__device__ __forceinline__ void cp_async16(uint32_t saddr, const void* gptr) {
    asm volatile("cp.async.cg.shared.global [%0], [%1], 16;"
                 :: "r"(saddr), "l"(gptr));
}

// ---------------------------- setup: pack weights ---------------------------
// Feature order k' : [0,16)=identity, [16,32)=sobel_x, [32,48)=sobel_y.
// Original w0 column for (type t, channel c) is 3c+t; 0.125 folded into sobel.
__device__ __forceinline__ float w0g(const float* w0, int n, int kp) {
    const int t = kp >> 4, c = kp & 15;
    const float v = w0[n * NK + 3 * c + t];
    return t ? v * 0.125f : v;
}

__global__ void nca_pack(const float* __restrict__ w0, const float* __restrict__ w1)
{
    const int idx = blockIdx.x * blockDim.x + threadIdx.x;
    if (idx < 3 * 8 * 32 * 2) {
        const int which = idx & 1;
        const int lane  = (idx >> 1) & 31;
        const int s2    = (idx >> 6) & 7;
        const int s     = idx >> 9;
        const int j = 2 * s2 + which;
        const int kp = 16 * s + 2 * (lane & 3);
        const int n = 8 * j + (lane >> 2);
        g_w0f[idx] = make_uint2(pk2h(w0g(w0, n, kp),     w0g(w0, n, kp + 1)),
                                pk2h(w0g(w0, n, kp + 8), w0g(w0, n, kp + 9)));
    }
    if (idx < 8 * 32 * 2) {
        const int jj   = idx & 1;
        const int lane = (idx >> 1) & 31;
        const int s    = idx >> 6;
        const int k = 16 * s + 2 * (lane & 3);
        const int n = 8 * jj + (lane >> 2);
        g_w1f[idx] = make_uint2(pk2h(w1[n * HID + k],     w1[n * HID + k + 1]),
                                pk2h(w1[n * HID + k + 8], w1[n * HID + k + 9]));
    }
}

// ------------------------------- Pass A ------------------------------------
#define TA_H 8
#define TA_W 32
#define HA_H (TA_H + 2)              // 10
#define HA_W (TA_W + 2)              // 34
#define TA_THREADS 256               // 8 warps, 32 pixels each (2 m16 tiles)
#define HA_PIX (HA_H * HA_W)         // 340
#define PLSTRIDE (HA_PIX * 4 + 4)    // 1364 u32 per half2 plane (8 ch each)
#define YSTRIDE 24                   // u32 words per Y row
#define YWARP   768                  // Y words per warp (32 rows * 24)
#define STG_PW  43                   // staged pixels per warp (43*8 >= 340)

// smem layout (32-bit words)
#define OFF_SXH  0                                   // 2 planes * 1364
#define OFF_SY   (OFF_SXH + 2 * PLSTRIDE)            // 2728 (also fp32 staging)
#define OFF_W0F  (OFF_SY + 256 * YSTRIDE)            // 8872
#define OFF_W1F  (OFF_W0F + 3072)                    // 11944
#define SMEM_A_WORDS (OFF_W1F + 1024)                // 12968
#define SMEM_A_BYTES (SMEM_A_WORDS * 4)              // 51872

__global__ __launch_bounds__(TA_THREADS, 3)
void nca_pass_a(const float* __restrict__ x,
                const float* __restrict__ rmask,
                float* __restrict__ out)
{
    extern __shared__ float smem[];
    uint32_t* sxh = (uint32_t*)smem + OFF_SXH;   // [2 planes][340 px][4 h2]
    uint32_t* sY  = (uint32_t*)smem + OFF_SY;
    uint32_t* w0f = (uint32_t*)smem + OFF_W0F;
    uint32_t* w1f = (uint32_t*)smem + OFF_W1F;

    const int tid  = threadIdx.x;
    const int lane = tid & 31;
    const int warp = tid >> 5;
    const int tig  = lane & 3;
    const int gid  = lane >> 2;

    const uint32_t smem_base = (uint32_t)__cvta_generic_to_shared(smem);

    // --- weight smem fill via cp.async (group A) ---
    {
        const uint32_t dst0 = smem_base + OFF_W0F * 4;
        #pragma unroll
        for (int i = 0; i < 3; i++)
            cp_async16(dst0 + (tid + 256 * i) * 16, (const char*)g_w0f + (tid + 256 * i) * 16);
        cp_async16(smem_base + OFF_W1F * 4 + tid * 16, (const char*)g_w1f + tid * 16);
        asm volatile("cp.async.commit_group;");
    }

    // --- block -> (b, ty0, tx0): two horizontally adjacent 8x32 tiles ---
    int bb = blockIdx.x;
    const int tx0 = (bb & 3) * 64;     bb >>= 2;     // IMG/64 = 4
    const int ty0 = (bb & 31) * TA_H;  bb >>= 5;     // IMG/8 = 32
    const int b = bb;
    const float* ximg = x + (size_t)b * IMG * IMG * CH;

    // --- tile0 halo fill: LDG float4 x4 -> half2 -> 2 STS.128 ---
    for (int p = tid; p < HA_PIX; p += TA_THREADS) {
        const int hy = ty0 + (p / HA_W) - 1;
        const int hx = tx0 + (p % HA_W) - 1;
        uint4 pl0 = make_uint4(0u, 0u, 0u, 0u);
        uint4 pl1 = make_uint4(0u, 0u, 0u, 0u);
        if ((unsigned)hy < IMG && (unsigned)hx < IMG) {
            const float4* src = (const float4*)(ximg + ((size_t)hy * IMG + hx) * CH);
            const float4 v0 = src[0], v1 = src[1], v2 = src[2], v3 = src[3];
            pl0 = make_uint4(pk2h(v0.x, v0.y), pk2h(v0.z, v0.w),
                             pk2h(v1.x, v1.y), pk2h(v1.z, v1.w));
            pl1 = make_uint4(pk2h(v2.x, v2.y), pk2h(v2.z, v2.w),
                             pk2h(v3.x, v3.y), pk2h(v3.z, v3.w));
        }
        *(uint4*)(sxh + p * 4) = pl0;
        *(uint4*)(sxh + PLSTRIDE + p * 4) = pl1;
    }
    asm volatile("cp.async.wait_group 0;");   // weights ready
    __syncthreads();                          // halo0 planes + weights visible

    #pragma unroll
    for (int tile = 0; tile < 2; tile++) {
        const int txt = tx0 + 32 * tile;

        // --- perceive: 1 thread = 1 pixel; half2 stencil, planes -> Y ---
        {
            const int pty = tid >> 5, ptx = tid & 31;
            const int pcen = (pty + 1) * HA_W + (ptx + 1);

            uint32_t feat[24];   // words: id[0..7], sx[8..15], sy[16..23]
            #pragma unroll
            for (int q = 0; q < 2; q++) {
                const uint32_t* pl = sxh + q * PLSTRIDE;
                const uint4 t0 = *(const uint4*)(pl + (pcen - HA_W - 1) * 4);
                const uint4 t1 = *(const uint4*)(pl + (pcen - HA_W    ) * 4);
                const uint4 t2 = *(const uint4*)(pl + (pcen - HA_W + 1) * 4);
                const uint4 t3 = *(const uint4*)(pl + (pcen        - 1) * 4);
                const uint4 t4 = *(const uint4*)(pl + (pcen           ) * 4);
                const uint4 t5 = *(const uint4*)(pl + (pcen        + 1) * 4);
                const uint4 t6 = *(const uint4*)(pl + (pcen + HA_W - 1) * 4);
                const uint4 t7 = *(const uint4*)(pl + (pcen + HA_W    ) * 4);
                const uint4 t8 = *(const uint4*)(pl + (pcen + HA_W + 1) * 4);

                #define NCA_STEN(W, WI)                                            \
                {                                                                  \
                    const int wi = q * 4 + (WI);                                   \
                    feat[wi] = t4.W;                                               \
                    const uint32_t sa = hsub2u(hadd2u(t2.W, t8.W),                 \
                                               hadd2u(t0.W, t6.W));                \
                    const uint32_t sd = hsub2u(t5.W, t3.W);                        \
                    feat[8 + wi] = hadd2u(sa, hadd2u(sd, sd));                     \
                    const uint32_t ya = hsub2u(hadd2u(t6.W, t8.W),                 \
                                               hadd2u(t0.W, t2.W));                \
                    const uint32_t yd = hsub2u(t7.W, t1.W);                        \
                    feat[16 + wi] = hadd2u(ya, hadd2u(yd, yd));                    \
                }
                NCA_STEN(x, 0) NCA_STEN(y, 1) NCA_STEN(z, 2) NCA_STEN(w, 3)
                #undef NCA_STEN
            }

            uint32_t* yrow = sY + tid * YSTRIDE;
            #pragma unroll
            for (int g = 0; g < 3; g++) {
                *(uint4*)(yrow + 8 * g)     = make_uint4(feat[8*g + 0], feat[8*g + 4],
                                                         feat[8*g + 1], feat[8*g + 5]);
                *(uint4*)(yrow + 8 * g + 4) = make_uint4(feat[8*g + 2], feat[8*g + 6],
                                                         feat[8*g + 3], feat[8*g + 7]);
            }
        }
        __syncwarp();   // Y rows are warp-private

        // --- rmask prefetch for this tile ---
        const int gy = ty0 + warp;
        const size_t rowbase = ((size_t)b * IMG + gy) * IMG + txt;
        float rmv[2][2];
        #pragma unroll
        for (int tt = 0; tt < 2; tt++)
            #pragma unroll
            for (int rr = 0; rr < 2; rr++)
                rmv[tt][rr] = rmask[rowbase + 16 * tt + gid + 8 * rr];

        // --- A-fragments for both m16 tiles (Y becomes dead after this) ---
        uint32_t a1f[2][3][4];
        #pragma unroll
        for (int tt = 0; tt < 2; tt++) {
            const int rb = warp * 32 + 16 * tt;
            #pragma unroll
            for (int s = 0; s < 3; s++) {
                const uint2 lo = *(const uint2*)(sY + (rb + gid)     * YSTRIDE + 8 * s + 2 * tig);
                const uint2 hi = *(const uint2*)(sY + (rb + gid + 8) * YSTRIDE + 8 * s + 2 * tig);
                a1f[tt][s][0] = lo.x;  a1f[tt][s][1] = hi.x;
                a1f[tt][s][2] = lo.y;  a1f[tt][s][3] = hi.y;
            }
        }

        // --- tile==0: prefetch tile1 halo (fp32) into this warp's Y region ---
        if (tile == 0) {
            #pragma unroll
            for (int it = 0; it < 2; it++) {
                const int pl_ = lane + it * 32;
                const int p = warp * STG_PW + pl_;
                if (pl_ < STG_PW && p < HA_PIX) {
                    const int hy = ty0 + (p / HA_W) - 1;
                    const int hx = tx0 + 32 + (p % HA_W) - 1;
                    if ((unsigned)hy < IMG && (unsigned)hx < IMG) {
                        const char* src = (const char*)(ximg + ((size_t)hy * IMG + hx) * CH);
                        const uint32_t dst = smem_base + (OFF_SY + warp * YWARP + pl_ * 16) * 4;
                        #pragma unroll
                        for (int q = 0; q < 4; q++)
                            cp_async16(dst + q * 16, src + q * 16);
                    }
                }
            }
            asm volatile("cp.async.commit_group;");
        }

        // --- fused GEMM1 -> relu/pack -> GEMM2 ---
        float d[2][2][4];
        #pragma unroll
        for (int tt = 0; tt < 2; tt++)
            #pragma unroll
            for (int jj = 0; jj < 2; jj++)
                #pragma unroll
                for (int q = 0; q < 4; q++) d[tt][jj][q] = 0.0f;

        #pragma unroll
        for (int s2 = 0; s2 < 8; s2++) {
            float aA0[4] = {0.f,0.f,0.f,0.f}, aA1[4] = {0.f,0.f,0.f,0.f};
            float aB0[4] = {0.f,0.f,0.f,0.f}, aB1[4] = {0.f,0.f,0.f,0.f};
            #pragma unroll
            for (int s = 0; s < 3; s++) {
                const uint4 bb4 = ((const uint4*)w0f)[(s * 8 + s2) * 32 + lane];
                mma_f16(aA0, a1f[0][s][0], a1f[0][s][1], a1f[0][s][2], a1f[0][s][3], bb4.x, bb4.y);
                mma_f16(aA1, a1f[0][s][0], a1f[0][s][1], a1f[0][s][2], a1f[0][s][3], bb4.z, bb4.w);
                mma_f16(aB0, a1f[1][s][0], a1f[1][s][1], a1f[1][s][2], a1f[1][s][3], bb4.x, bb4.y);
                mma_f16(aB1, a1f[1][s][0], a1f[1][s][1], a1f[1][s][2], a1f[1][s][3], bb4.z, bb4.w);
            }
            const uint4 b2 = ((const uint4*)w1f)[s2 * 32 + lane];
            {
                const uint32_t f0 = pk2h(fmaxf(aA0[0], 0.f), fmaxf(aA0[1], 0.f));
                const uint32_t f1 = pk2h(fmaxf(aA0[2], 0.f), fmaxf(aA0[3], 0.f));
                const uint32_t f2 = pk2h(fmaxf(aA1[0], 0.f), fmaxf(aA1[1], 0.f));
                const uint32_t f3 = pk2h(fmaxf(aA1[2], 0.f), fmaxf(aA1[3], 0.f));
                mma_f16(d[0][0], f0, f1, f2, f3, b2.x, b2.y);
                mma_f16(d[0][1], f0, f1, f2, f3, b2.z, b2.w);
            }
            {
                const uint32_t f0 = pk2h(fmaxf(aB0[0], 0.f), fmaxf(aB0[1], 0.f));
                const uint32_t f1 = pk2h(fmaxf(aB0[2], 0.f), fmaxf(aB0[3], 0.f));
                const uint32_t f2 = pk2h(fmaxf(aB1[0], 0.f), fmaxf(aB1[1], 0.f));
                const uint32_t f3 = pk2h(fmaxf(aB1[2], 0.f), fmaxf(aB1[3], 0.f));
                mma_f16(d[1][0], f0, f1, f2, f3, b2.x, b2.y);
                mma_f16(d[1][1], f0, f1, f2, f3, b2.z, b2.w);
            }
        }

        // --- epilogue: x_new = x(gmem, fp32 exact) + dx*(rand<=0.5) -> OUT ---
        #pragma unroll
        for (int tt = 0; tt < 2; tt++) {
            #pragma unroll
            for (int rr = 0; rr < 2; rr++) {
                const int ptx = 16 * tt + gid + 8 * rr;
                const size_t pix = rowbase + ptx;
                const float upd = (rmv[tt][rr] <= 0.5f) ? 1.0f : 0.0f;
                #pragma unroll
                for (int jj = 0; jj < 2; jj++) {
                    const int ch = 8 * jj + 2 * tig;
                    const float2 xv = *(const float2*)(x + pix * CH + ch);
                    float2 v;
                    v.x = xv.x + d[tt][jj][2 * rr + 0] * upd;
                    v.y = xv.y + d[tt][jj][2 * rr + 1] * upd;
                    *(float2*)(out + pix * CH + ch) = v;
                    if (jj == 0 && tig == 1) {       // ch pair (2,3): alpha = .y
                        g_aon[pix] = pk2bf(xv.y, v.y);   // (old, new) bf16x2
                    }
                }
            }
        }

        // --- tile==0: convert staged tile1 halo (fp32 smem) -> half2 planes ---
        if (tile == 0) {
            asm volatile("cp.async.wait_group 0;");
            __syncthreads();   // staging visible block-wide; everyone past MMA0
            for (int p = tid; p < HA_PIX; p += TA_THREADS) {
                const int hy = ty0 + (p / HA_W) - 1;
                const int hx = tx0 + 32 + (p % HA_W) - 1;
                uint4 pl0 = make_uint4(0u, 0u, 0u, 0u);
                uint4 pl1 = make_uint4(0u, 0u, 0u, 0u);
                if ((unsigned)hy < IMG && (unsigned)hx < IMG) {
                    const int pw = p / STG_PW;
                    const int po = p - pw * STG_PW;
                    const float4* st = (const float4*)(sY + pw * YWARP + po * 16);
                    const float4 v0 = st[0], v1 = st[1], v2 = st[2], v3 = st[3];
                    pl0 = make_uint4(pk2h(v0.x, v0.y), pk2h(v0.z, v0.w),
                                     pk2h(v1.x, v1.y), pk2h(v1.z, v1.w));
                    pl1 = make_uint4(pk2h(v2.x, v2.y), pk2h(v2.z, v2.w),
                                     pk2h(v3.x, v3.y), pk2h(v3.z, v3.w));
                }
                *(uint4*)(sxh + p * 4) = pl0;
                *(uint4*)(sxh + PLSTRIDE + p * 4) = pl1;
            }
            __syncthreads();   // planes1 ready for tile1 perceive
        }
    }
}

// ------------------------------- Pass B (fix-up, 2 px/thread) ---------------
#define TB_H 8
#define TB_W 64
#define HB_H (TB_H + 2)              // 10
#define HB_W (TB_W + 2)              // 66
#define HB_PIX (HB_H * HB_W)         // 660
#define TB_THREADS 256               // 8 warps; warp = row, lane = col-pair

__global__ __launch_bounds__(TB_THREADS)
void nca_pass_b(float* __restrict__ out)
{
    __shared__ uint32_t saon[HB_PIX];

    const int tid = threadIdx.x;
    int bb = blockIdx.x;
    const int tx0 = (bb & 3) * TB_W;   bb >>= 2;     // IMG/TB_W = 4
    const int ty0 = (bb & 31) * TB_H;  bb >>= 5;     // IMG/TB_H = 32
    const int b = bb;
    const size_t ibase = (size_t)b * IMG * IMG;

    for (int p = tid; p < HB_PIX; p += TB_THREADS) {
        const int hy = ty0 + (p / HB_W) - 1;
        const int hx = tx0 + (p % HB_W) - 1;
        saon[p] = ((unsigned)hy < IMG && (unsigned)hx < IMG)
                    ? g_aon[ibase + (size_t)hy * IMG + hx]
                    : 0u;
    }
    __syncthreads();

    const int ty  = tid >> 5;         // pixel row within tile
    const int txp = tid & 31;         // col-pair index (cols 2txp, 2txp+1)

    __nv_bfloat162 vc0, vc1, vc2, vc3;
    {
        const uint32_t* r0 = saon + (ty + 0) * HB_W + 2 * txp;
        const uint32_t* r1 = saon + (ty + 1) * HB_W + 2 * txp;
        const uint32_t* r2 = saon + (ty + 2) * HB_W + 2 * txp;
        const uint2 a0 = *(const uint2*)r0,       b0 = *(const uint2*)(r0 + 2);
        const uint2 a1 = *(const uint2*)r1,       b1 = *(const uint2*)(r1 + 2);
        const uint2 a2 = *(const uint2*)r2,       b2 = *(const uint2*)(r2 + 2);
        #define BF2(u) (*(const __nv_bfloat162*)&(u))
        vc0 = bmax2(bmax2(BF2(a0.x), BF2(a1.x)), BF2(a2.x));
        vc1 = bmax2(bmax2(BF2(a0.y), BF2(a1.y)), BF2(a2.y));
        vc2 = bmax2(bmax2(BF2(b0.x), BF2(b1.x)), BF2(b2.x));
        vc3 = bmax2(bmax2(BF2(b0.y), BF2(b1.y)), BF2(b2.y));
        #undef BF2
    }
    const __nv_bfloat162 m12 = bmax2(vc1, vc2);
    const __nv_bfloat162 m0  = bmax2(m12, vc0);   // pixel col 2txp
    const __nv_bfloat162 m1  = bmax2(m12, vc3);   // pixel col 2txp+1

    const size_t rowpix = ibase + (size_t)(ty0 + ty) * IMG + tx0 + 2 * txp;
    const float4 z = make_float4(0.f, 0.f, 0.f, 0.f);

    if (!(__bfloat162float(m0.x) > 0.1f && __bfloat162float(m0.y) > 0.1f)) {
        float4* dst = (float4*)(out + rowpix * CH);
        dst[0] = z; dst[1] = z; dst[2] = z; dst[3] = z;
    }
    if (!(__bfloat162float(m1.x) > 0.1f && __bfloat162float(m1.y) > 0.1f)) {
        float4* dst = (float4*)(out + (rowpix + 1) * CH);
        dst[0] = z; dst[1] = z; dst[2] = z; dst[3] = z;
    }
}

// ----------------------------------------------------------------------------
extern "C" void kernel_launch(void* const* d_in, const int* in_sizes, int n_in,
                              void* d_out, int out_size)
{
    (void)in_sizes; (void)n_in; (void)out_size;
    const float* x  = (const float*)d_in[0];
    const float* w0 = (const float*)d_in[1];
    const float* w1 = (const float*)d_in[2];
    const float* rm = (const float*)d_in[3];
    float* out = (float*)d_out;

    cudaFuncSetAttribute(nca_pass_a, cudaFuncAttributeMaxDynamicSharedMemorySize,
                         SMEM_A_BYTES);

    const int grid_a = BATCH * (IMG / TA_H) * (IMG / 64);   // 2048 (2 tiles/block)
    const int grid_b = BATCH * (IMG / TB_H) * (IMG / TB_W); // 2048

    nca_pack<<<12, 128>>>(w0, w1);
    nca_pass_a<<<grid_a, TA_THREADS, SMEM_A_BYTES>>>(x, rm, out);
    nca_pass_b<<<grid_b, TB_THREADS>>>(out);
}

// round 16
// speedup vs baseline: 1.0063x; 1.0063x over previous
#include <cuda_runtime.h>
#include <cuda_fp16.h>
#include <cuda_bf16.h>
#include <math.h>
#include <stdint.h>

// ---------------------------------------------------------------------------
// Neural CA step, fp16 mma.sync (m16n8k16), fp32 accumulate. TWO launches.
//   Pass A: 8x32 px tile/block, 32 px/warp (two m16 tiles share B-frags),
//           occupancy 3, halo as half2 planes. Weight fragments computed
//           in-block from global w0/w1 (L2-hot, no pack kernel, no extra
//           barriers). x_new direct to out; alphas as bf16x2.
//   Pass B: fix-up — 2 px/thread shared vertical maxes; zero dead pixels.
// ---------------------------------------------------------------------------

#define CH    16
#define NK    48
#define HID   128
#define IMG   256
#define BATCH 16

__device__ uint32_t g_aon[(size_t)BATCH * IMG * IMG];  // bf16x2 (alpha_old, alpha_new)

__device__ __forceinline__ uint32_t pk2h(float lo, float hi) {
    __half2 h = __floats2half2_rn(lo, hi);
    return *(uint32_t*)&h;
}
__device__ __forceinline__ uint32_t pk2bf(float lo, float hi) {
    __nv_bfloat162 h = __floats2bfloat162_rn(lo, hi);
    return *(uint32_t*)&h;
}
__device__ __forceinline__ uint32_t hadd2u(uint32_t a, uint32_t b) {
    uint32_t r; asm("add.f16x2 %0, %1, %2;" : "=r"(r) : "r"(a), "r"(b)); return r;
}
__device__ __forceinline__ uint32_t hsub2u(uint32_t a, uint32_t b) {
    uint32_t r; asm("sub.f16x2 %0, %1, %2;" : "=r"(r) : "r"(a), "r"(b)); return r;
}
__device__ __forceinline__ __nv_bfloat162 bmax2(__nv_bfloat162 a, __nv_bfloat162 b) {
    return __hmax2(a, b);
}

__device__ __forceinline__ void mma_f16(float c[4],
                                        uint32_t a0, uint32_t a1, uint32_t a2, uint32_t a3,
                                        uint32_t b0, uint32_t b1) {
    asm volatile(
        "mma.sync.aligned.m16n8k16.row.col.f32.f16.f16.f32 "
        "{%0,%1,%2,%3}, {%4,%5,%6,%7}, {%8,%9}, {%0,%1,%2,%3};"
        : "+f"(c[0]), "+f"(c[1]), "+f"(c[2]), "+f"(c[3])
        : "r"(a0), "r"(a1), "r"(a2), "r"(a3), "r"(b0), "r"(b1));
}

// Feature order k' : [0,16)=identity, [16,32)=sobel_x, [32,48)=sobel_y.
// Original w0 column for (type t, channel c) is 3c+t; 0.125 folded into sobel.
__device__ __forceinline__ float w0g(const float* __restrict__ w0, int n, int kp) {
    const int t = kp >> 4, c = kp & 15;
    const float v = __ldg(w0 + n * NK + 3 * c + t);
    return t ? v * 0.125f : v;
}

// ------------------------------- Pass A ------------------------------------
#define TA_H 8
#define TA_W 32
#define HA_H (TA_H + 2)              // 10
#define HA_W (TA_W + 2)              // 34
#define TA_THREADS 256               // 8 warps, 32 pixels each (2 m16 tiles)
#define HA_PIX (HA_H * HA_W)         // 340
#define PLSTRIDE (HA_PIX * 4 + 4)    // 1364 u32 per half2 plane (8 ch each)
#define YSTRIDE 24                   // u32 words per Y row

// smem layout (32-bit words)
#define OFF_SXH  0                                   // 2 planes * 1364
#define OFF_SY   (OFF_SXH + 2 * PLSTRIDE)            // 2728
#define OFF_W0F  (OFF_SY + 256 * YSTRIDE)            // 8872
#define OFF_W1F  (OFF_W0F + 3072)                    // 11944
#define SMEM_A_WORDS (OFF_W1F + 1024)                // 12968
#define SMEM_A_BYTES (SMEM_A_WORDS * 4)              // 51872

__global__ __launch_bounds__(TA_THREADS, 3)
void nca_pass_a(const float* __restrict__ x,
                const float* __restrict__ w0gm,
                const float* __restrict__ w1gm,
                const float* __restrict__ rmask,
                float* __restrict__ out)
{
    extern __shared__ float smem[];
    uint32_t* sxh = (uint32_t*)smem + OFF_SXH;   // [2 planes][340 px][4 h2]
    uint32_t* sY  = (uint32_t*)smem + OFF_SY;
    uint32_t* w0f = (uint32_t*)smem + OFF_W0F;
    uint32_t* w1f = (uint32_t*)smem + OFF_W1F;

    const int tid  = threadIdx.x;
    const int lane = tid & 31;
    const int warp = tid >> 5;
    const int tig  = lane & 3;
    const int gid  = lane >> 2;

    // --- block -> (b, ty0, tx0) ---
    int bb = blockIdx.x;
    const int tx0 = (bb & 7) * TA_W;   bb >>= 3;     // IMG/TA_W = 8
    const int ty0 = (bb & 31) * TA_H;  bb >>= 5;     // IMG/TA_H = 32
    const int b = bb;
    const float* ximg = x + (size_t)b * IMG * IMG * CH;

    // --- halo fill: LDG float4 x4 -> half2 -> 2 STS.128 (one per plane) ---
    for (int p = tid; p < HA_PIX; p += TA_THREADS) {
        const int hy = ty0 + (p / HA_W) - 1;
        const int hx = tx0 + (p % HA_W) - 1;
        uint4 pl0 = make_uint4(0u, 0u, 0u, 0u);
        uint4 pl1 = make_uint4(0u, 0u, 0u, 0u);
        if ((unsigned)hy < IMG && (unsigned)hx < IMG) {
            const float4* src = (const float4*)(ximg + ((size_t)hy * IMG + hx) * CH);
            const float4 v0 = src[0], v1 = src[1], v2 = src[2], v3 = src[3];
            pl0 = make_uint4(pk2h(v0.x, v0.y), pk2h(v0.z, v0.w),
                             pk2h(v1.x, v1.y), pk2h(v1.z, v1.w));
            pl1 = make_uint4(pk2h(v2.x, v2.y), pk2h(v2.z, v2.w),
                             pk2h(v3.x, v3.y), pk2h(v3.z, v3.w));
        }
        *(uint4*)(sxh + p * 4) = pl0;
        *(uint4*)(sxh + PLSTRIDE + p * 4) = pl1;
    }

    // --- weight fragments computed in-block from global (L2-hot) ---
    // GEMM1: 1536 uint2 elems, 6 per thread. Same math as the old pack kernel.
    {
        uint2* w0fp = (uint2*)w0f;
        #pragma unroll
        for (int i = 0; i < 6; i++) {
            const int e = tid + 256 * i;
            const int which = e & 1, ln = (e >> 1) & 31;
            const int s2 = (e >> 6) & 7, s = e >> 9;
            const int j = 2 * s2 + which;
            const int kp = 16 * s + 2 * (ln & 3);
            const int n = 8 * j + (ln >> 2);
            w0fp[e] = make_uint2(pk2h(w0g(w0gm, n, kp),     w0g(w0gm, n, kp + 1)),
                                 pk2h(w0g(w0gm, n, kp + 8), w0g(w0gm, n, kp + 9)));
        }
        // GEMM2: 512 uint2 elems, 2 per thread.
        uint2* w1fp = (uint2*)w1f;
        #pragma unroll
        for (int i = 0; i < 2; i++) {
            const int e = tid + 256 * i;
            const int jj = e & 1, ln = (e >> 1) & 31, s = e >> 6;
            const int k = 16 * s + 2 * (ln & 3);
            const int n = 8 * jj + (ln >> 2);
            w1fp[e] = make_uint2(pk2h(__ldg(w1gm + n * HID + k),
                                      __ldg(w1gm + n * HID + k + 1)),
                                 pk2h(__ldg(w1gm + n * HID + k + 8),
                                      __ldg(w1gm + n * HID + k + 9)));
        }
    }
    __syncthreads();   // halo planes + weight fragments visible

    // --- perceive: 1 thread = 1 pixel; half2 stencil, 9 taps x 2 planes ---
    {
        const int pty = tid >> 5, ptx = tid & 31;
        const int pcen = (pty + 1) * HA_W + (ptx + 1);

        uint32_t feat[24];   // words: id[0..7], sx[8..15], sy[16..23]
        #pragma unroll
        for (int q = 0; q < 2; q++) {
            const uint32_t* pl = sxh + q * PLSTRIDE;
            const uint4 t0 = *(const uint4*)(pl + (pcen - HA_W - 1) * 4);
            const uint4 t1 = *(const uint4*)(pl + (pcen - HA_W    ) * 4);
            const uint4 t2 = *(const uint4*)(pl + (pcen - HA_W + 1) * 4);
            const uint4 t3 = *(const uint4*)(pl + (pcen        - 1) * 4);
            const uint4 t4 = *(const uint4*)(pl + (pcen           ) * 4);
            const uint4 t5 = *(const uint4*)(pl + (pcen        + 1) * 4);
            const uint4 t6 = *(const uint4*)(pl + (pcen + HA_W - 1) * 4);
            const uint4 t7 = *(const uint4*)(pl + (pcen + HA_W    ) * 4);
            const uint4 t8 = *(const uint4*)(pl + (pcen + HA_W + 1) * 4);

            #define NCA_STEN(W, WI)                                            \
            {                                                                  \
                const int wi = q * 4 + (WI);                                   \
                feat[wi] = t4.W;                                               \
                const uint32_t sa = hsub2u(hadd2u(t2.W, t8.W),                 \
                                           hadd2u(t0.W, t6.W));                \
                const uint32_t sd = hsub2u(t5.W, t3.W);                        \
                feat[8 + wi] = hadd2u(sa, hadd2u(sd, sd));                     \
                const uint32_t ya = hsub2u(hadd2u(t6.W, t8.W),                 \
                                           hadd2u(t0.W, t2.W));                \
                const uint32_t yd = hsub2u(t7.W, t1.W);                        \
                feat[16 + wi] = hadd2u(ya, hadd2u(yd, yd));                    \
            }
            NCA_STEN(x, 0) NCA_STEN(y, 1) NCA_STEN(z, 2) NCA_STEN(w, 3)
            #undef NCA_STEN
        }

        // Y store with physw permutation baked in
        uint32_t* yrow = sY + tid * YSTRIDE;
        #pragma unroll
        for (int g = 0; g < 3; g++) {
            *(uint4*)(yrow + 8 * g)     = make_uint4(feat[8*g + 0], feat[8*g + 4],
                                                     feat[8*g + 1], feat[8*g + 5]);
            *(uint4*)(yrow + 8 * g + 4) = make_uint4(feat[8*g + 2], feat[8*g + 6],
                                                     feat[8*g + 3], feat[8*g + 7]);
        }
    }
    // Y rows consumed by this warp were written only by this warp's threads.
    __syncwarp();

    // --- prefetch rmask (4 pixels per thread: 2 tiles x 2 rows) ---
    const int gy = ty0 + warp;
    const size_t rowbase = ((size_t)b * IMG + gy) * IMG + tx0;
    float rmv[2][2];
    #pragma unroll
    for (int tt = 0; tt < 2; tt++)
        #pragma unroll
        for (int rr = 0; rr < 2; rr++)
            rmv[tt][rr] = rmask[rowbase + 16 * tt + gid + 8 * rr];

    // --- A-fragments for both m16 tiles ---
    uint32_t a1f[2][3][4];
    #pragma unroll
    for (int tt = 0; tt < 2; tt++) {
        const int rb = warp * 32 + 16 * tt;
        #pragma unroll
        for (int s = 0; s < 3; s++) {
            const uint2 lo = *(const uint2*)(sY + (rb + gid)     * YSTRIDE + 8 * s + 2 * tig);
            const uint2 hi = *(const uint2*)(sY + (rb + gid + 8) * YSTRIDE + 8 * s + 2 * tig);
            a1f[tt][s][0] = lo.x;  a1f[tt][s][1] = hi.x;
            a1f[tt][s][2] = lo.y;  a1f[tt][s][3] = hi.y;
        }
    }

    // --- fused GEMM1 -> relu/pack -> GEMM2, B-frags shared by both tiles ---
    float d[2][2][4];
    #pragma unroll
    for (int tt = 0; tt < 2; tt++)
        #pragma unroll
        for (int jj = 0; jj < 2; jj++)
            #pragma unroll
            for (int q = 0; q < 4; q++) d[tt][jj][q] = 0.0f;

    #pragma unroll
    for (int s2 = 0; s2 < 8; s2++) {
        float aA0[4] = {0.f,0.f,0.f,0.f}, aA1[4] = {0.f,0.f,0.f,0.f};
        float aB0[4] = {0.f,0.f,0.f,0.f}, aB1[4] = {0.f,0.f,0.f,0.f};
        #pragma unroll
        for (int s = 0; s < 3; s++) {
            const uint4 bb4 = ((const uint4*)w0f)[(s * 8 + s2) * 32 + lane];
            mma_f16(aA0, a1f[0][s][0], a1f[0][s][1], a1f[0][s][2], a1f[0][s][3], bb4.x, bb4.y);
            mma_f16(aA1, a1f[0][s][0], a1f[0][s][1], a1f[0][s][2], a1f[0][s][3], bb4.z, bb4.w);
            mma_f16(aB0, a1f[1][s][0], a1f[1][s][1], a1f[1][s][2], a1f[1][s][3], bb4.x, bb4.y);
            mma_f16(aB1, a1f[1][s][0], a1f[1][s][1], a1f[1][s][2], a1f[1][s][3], bb4.z, bb4.w);
        }
        const uint4 b2 = ((const uint4*)w1f)[s2 * 32 + lane];
        {
            const uint32_t f0 = pk2h(fmaxf(aA0[0], 0.f), fmaxf(aA0[1], 0.f));
            const uint32_t f1 = pk2h(fmaxf(aA0[2], 0.f), fmaxf(aA0[3], 0.f));
            const uint32_t f2 = pk2h(fmaxf(aA1[0], 0.f), fmaxf(aA1[1], 0.f));
            const uint32_t f3 = pk2h(fmaxf(aA1[2], 0.f), fmaxf(aA1[3], 0.f));
            mma_f16(d[0][0], f0, f1, f2, f3, b2.x, b2.y);
            mma_f16(d[0][1], f0, f1, f2, f3, b2.z, b2.w);
        }
        {
            const uint32_t f0 = pk2h(fmaxf(aB0[0], 0.f), fmaxf(aB0[1], 0.f));
            const uint32_t f1 = pk2h(fmaxf(aB0[2], 0.f), fmaxf(aB0[3], 0.f));
            const uint32_t f2 = pk2h(fmaxf(aB1[0], 0.f), fmaxf(aB1[1], 0.f));
            const uint32_t f3 = pk2h(fmaxf(aB1[2], 0.f), fmaxf(aB1[3], 0.f));
            mma_f16(d[1][0], f0, f1, f2, f3, b2.x, b2.y);
            mma_f16(d[1][1], f0, f1, f2, f3, b2.z, b2.w);
        }
    }

    // --- epilogue: x_new = x(gmem, fp32 exact) + dx*(rand<=0.5) -> OUT ---
    #pragma unroll
    for (int tt = 0; tt < 2; tt++) {
        #pragma unroll
        for (int rr = 0; rr < 2; rr++) {
            const int ptx = 16 * tt + gid + 8 * rr;
            const size_t pix = rowbase + ptx;
            const float upd = (rmv[tt][rr] <= 0.5f) ? 1.0f : 0.0f;
            #pragma unroll
            for (int jj = 0; jj < 2; jj++) {
                const int ch = 8 * jj + 2 * tig;
                const float2 xv = *(const float2*)(x + pix * CH + ch);
                float2 v;
                v.x = xv.x + d[tt][jj][2 * rr + 0] * upd;
                v.y = xv.y + d[tt][jj][2 * rr + 1] * upd;
                *(float2*)(out + pix * CH + ch) = v;
                if (jj == 0 && tig == 1) {       // ch pair (2,3): alpha = .y
                    g_aon[pix] = pk2bf(xv.y, v.y);   // (old, new) bf16x2
                }
            }
        }
    }
}

// ------------------------------- Pass B (fix-up, 2 px/thread) ---------------
#define TB_H 8
#define TB_W 64
#define HB_H (TB_H + 2)              // 10
#define HB_W (TB_W + 2)              // 66
#define HB_PIX (HB_H * HB_W)         // 660
#define TB_THREADS 256               // 8 warps; warp = row, lane = col-pair

__global__ __launch_bounds__(TB_THREADS)
void nca_pass_b(float* __restrict__ out)
{
    __shared__ uint32_t saon[HB_PIX];

    const int tid = threadIdx.x;
    int bb = blockIdx.x;
    const int tx0 = (bb & 3) * TB_W;   bb >>= 2;     // IMG/TB_W = 4
    const int ty0 = (bb & 31) * TB_H;  bb >>= 5;     // IMG/TB_H = 32
    const int b = bb;
    const size_t ibase = (size_t)b * IMG * IMG;

    for (int p = tid; p < HB_PIX; p += TB_THREADS) {
        const int hy = ty0 + (p / HB_W) - 1;
        const int hx = tx0 + (p % HB_W) - 1;
        saon[p] = ((unsigned)hy < IMG && (unsigned)hx < IMG)
                    ? g_aon[ibase + (size_t)hy * IMG + hx]
                    : 0u;
    }
    __syncthreads();

    const int ty  = tid >> 5;         // pixel row within tile
    const int txp = tid & 31;         // col-pair index (cols 2txp, 2txp+1)

    __nv_bfloat162 vc0, vc1, vc2, vc3;
    {
        const uint32_t* r0 = saon + (ty + 0) * HB_W + 2 * txp;
        const uint32_t* r1 = saon + (ty + 1) * HB_W + 2 * txp;
        const uint32_t* r2 = saon + (ty + 2) * HB_W + 2 * txp;
        const uint2 a0 = *(const uint2*)r0,       b0 = *(const uint2*)(r0 + 2);
        const uint2 a1 = *(const uint2*)r1,       b1 = *(const uint2*)(r1 + 2);
        const uint2 a2 = *(const uint2*)r2,       b2 = *(const uint2*)(r2 + 2);
        #define BF2(u) (*(const __nv_bfloat162*)&(u))
        vc0 = bmax2(bmax2(BF2(a0.x), BF2(a1.x)), BF2(a2.x));
        vc1 = bmax2(bmax2(BF2(a0.y), BF2(a1.y)), BF2(a2.y));
        vc2 = bmax2(bmax2(BF2(b0.x), BF2(b1.x)), BF2(b2.x));
        vc3 = bmax2(bmax2(BF2(b0.y), BF2(b1.y)), BF2(b2.y));
        #undef BF2
    }
    const __nv_bfloat162 m12 = bmax2(vc1, vc2);
    const __nv_bfloat162 m0  = bmax2(m12, vc0);   // pixel col 2txp
    const __nv_bfloat162 m1  = bmax2(m12, vc3);   // pixel col 2txp+1

    const size_t rowpix = ibase + (size_t)(ty0 + ty) * IMG + tx0 + 2 * txp;
    const float4 z = make_float4(0.f, 0.f, 0.f, 0.f);

    if (!(__bfloat162float(m0.x) > 0.1f && __bfloat162float(m0.y) > 0.1f)) {
        float4* dst = (float4*)(out + rowpix * CH);
        dst[0] = z; dst[1] = z; dst[2] = z; dst[3] = z;
    }
    if (!(__bfloat162float(m1.x) > 0.1f && __bfloat162float(m1.y) > 0.1f)) {
        float4* dst = (float4*)(out + (rowpix + 1) * CH);
        dst[0] = z; dst[1] = z; dst[2] = z; dst[3] = z;
    }
}

// ----------------------------------------------------------------------------
extern "C" void kernel_launch(void* const* d_in, const int* in_sizes, int n_in,
                              void* d_out, int out_size)
{
    (void)in_sizes; (void)n_in; (void)out_size;
    const float* x  = (const float*)d_in[0];
    const float* w0 = (const float*)d_in[1];
    const float* w1 = (const float*)d_in[2];
    const float* rm = (const float*)d_in[3];
    float* out = (float*)d_out;

    cudaFuncSetAttribute(nca_pass_a, cudaFuncAttributeMaxDynamicSharedMemorySize,
                         SMEM_A_BYTES);

    const int grid_a = BATCH * (IMG / TA_H) * (IMG / TA_W); // 4096
    const int grid_b = BATCH * (IMG / TB_H) * (IMG / TB_W); // 2048

    nca_pass_a<<<grid_a, TA_THREADS, SMEM_A_BYTES>>>(x, w0, w1, rm, out);
    nca_pass_b<<<grid_b, TB_THREADS>>>(out);
}

// round 17
// speedup vs baseline: 1.2387x; 1.2309x over previous
#include <cuda_runtime.h>
#include <cuda_fp16.h>
#include <cuda_bf16.h>
#include <math.h>
#include <stdint.h>

// ---------------------------------------------------------------------------
// Neural CA step, fp16 mma.sync (m16n8k16), fp32 accumulate.
//   Pack:   one-time weight fragment packing (w0 reorder + sobel fold).
//   Pass A: 8x32 px tile/block, 32 px/warp (two m16 tiles share B-frags),
//           occupancy 3, halo as half2 planes, cp.async weights, syncwarp
//           Y handoff. x_new direct to out; alphas as bf16x2.  [R14 proven]
//   Pass B: fix-up, SMEM-FREE — warp=row, lane=pixel pair; 3 coalesced
//           LDG.64 vertical maxes + lane shuffles for side columns.
// ---------------------------------------------------------------------------

#define CH    16
#define NK    48
#define HID   128
#define IMG   256
#define BATCH 16

__device__ uint32_t g_aon[(size_t)BATCH * IMG * IMG];  // bf16x2 (alpha_old, alpha_new)
__device__ uint2 g_w0f[3 * 8 * 32 * 2];   // uint4-pairable GEMM1 B-frags
__device__ uint2 g_w1f[8 * 32 * 2];       // uint4-pairable GEMM2 B-frags

__device__ __forceinline__ uint32_t pk2h(float lo, float hi) {
    __half2 h = __floats2half2_rn(lo, hi);
    return *(uint32_t*)&h;
}
__device__ __forceinline__ uint32_t pk2bf(float lo, float hi) {
    __nv_bfloat162 h = __floats2bfloat162_rn(lo, hi);
    return *(uint32_t*)&h;
}
__device__ __forceinline__ uint32_t hadd2u(uint32_t a, uint32_t b) {
    uint32_t r; asm("add.f16x2 %0, %1, %2;" : "=r"(r) : "r"(a), "r"(b)); return r;
}
__device__ __forceinline__ uint32_t hsub2u(uint32_t a, uint32_t b) {
    uint32_t r; asm("sub.f16x2 %0, %1, %2;" : "=r"(r) : "r"(a), "r"(b)); return r;
}
__device__ __forceinline__ __nv_bfloat162 bmax2(__nv_bfloat162 a, __nv_bfloat162 b) {
    return __hmax2(a, b);
}
__device__ __forceinline__ __nv_bfloat162 u2bf2(uint32_t u) {
    __nv_bfloat162 t; *(uint32_t*)&t = u; return t;
}
__device__ __forceinline__ uint32_t bf22u(__nv_bfloat162 v) {
    return *(uint32_t*)&v;
}

__device__ __forceinline__ void mma_f16(float c[4],
                                        uint32_t a0, uint32_t a1, uint32_t a2, uint32_t a3,
                                        uint32_t b0, uint32_t b1) {
    asm volatile(
        "mma.sync.aligned.m16n8k16.row.col.f32.f16.f16.f32 "
        "{%0,%1,%2,%3}, {%4,%5,%6,%7}, {%8,%9}, {%0,%1,%2,%3};"
        : "+f"(c[0]), "+f"(c[1]), "+f"(c[2]), "+f"(c[3])
        : "r"(a0), "r"(a1), "r"(a2), "r"(a3), "r"(b0), "r"(b1));
}

__device__ __forceinline__ void cp_async16(uint32_t saddr, const void* gptr) {
    asm volatile("cp.async.cg.shared.global [%0], [%1], 16;"
                 :: "r"(saddr), "l"(gptr));
}

// ---------------------------- setup: pack weights ---------------------------
// Feature order k' : [0,16)=identity, [16,32)=sobel_x, [32,48)=sobel_y.
// Original w0 column for (type t, channel c) is 3c+t; 0.125 folded into sobel.
__device__ __forceinline__ float w0g(const float* w0, int n, int kp) {
    const int t = kp >> 4, c = kp & 15;
    const float v = w0[n * NK + 3 * c + t];
    return t ? v * 0.125f : v;
}

__global__ void nca_pack(const float* __restrict__ w0, const float* __restrict__ w1)
{
    const int idx = blockIdx.x * blockDim.x + threadIdx.x;
    if (idx < 3 * 8 * 32 * 2) {
        const int which = idx & 1;
        const int lane  = (idx >> 1) & 31;
        const int s2    = (idx >> 6) & 7;
        const int s     = idx >> 9;
        const int j = 2 * s2 + which;
        const int kp = 16 * s + 2 * (lane & 3);
        const int n = 8 * j + (lane >> 2);
        g_w0f[idx] = make_uint2(pk2h(w0g(w0, n, kp),     w0g(w0, n, kp + 1)),
                                pk2h(w0g(w0, n, kp + 8), w0g(w0, n, kp + 9)));
    }
    if (idx < 8 * 32 * 2) {
        const int jj   = idx & 1;
        const int lane = (idx >> 1) & 31;
        const int s    = idx >> 6;
        const int k = 16 * s + 2 * (lane & 3);
        const int n = 8 * jj + (lane >> 2);
        g_w1f[idx] = make_uint2(pk2h(w1[n * HID + k],     w1[n * HID + k + 1]),
                                pk2h(w1[n * HID + k + 8], w1[n * HID + k + 9]));
    }
}

// ------------------------------- Pass A ------------------------------------
#define TA_H 8
#define TA_W 32
#define HA_H (TA_H + 2)              // 10
#define HA_W (TA_W + 2)              // 34
#define TA_THREADS 256               // 8 warps, 32 pixels each (2 m16 tiles)
#define HA_PIX (HA_H * HA_W)         // 340
#define PLSTRIDE (HA_PIX * 4 + 4)    // 1364 u32 per half2 plane (8 ch each)
#define YSTRIDE 24                   // u32 words per Y row

// smem layout (32-bit words)
#define OFF_SXH  0                                   // 2 planes * 1364
#define OFF_SY   (OFF_SXH + 2 * PLSTRIDE)            // 2728
#define OFF_W0F  (OFF_SY + 256 * YSTRIDE)            // 8872
#define OFF_W1F  (OFF_W0F + 3072)                    // 11944
#define SMEM_A_WORDS (OFF_W1F + 1024)                // 12968
#define SMEM_A_BYTES (SMEM_A_WORDS * 4)              // 51872

__global__ __launch_bounds__(TA_THREADS, 3)
void nca_pass_a(const float* __restrict__ x,
                const float* __restrict__ rmask,
                float* __restrict__ out)
{
    extern __shared__ float smem[];
    uint32_t* sxh = (uint32_t*)smem + OFF_SXH;   // [2 planes][340 px][4 h2]
    uint32_t* sY  = (uint32_t*)smem + OFF_SY;
    uint32_t* w0f = (uint32_t*)smem + OFF_W0F;
    uint32_t* w1f = (uint32_t*)smem + OFF_W1F;

    const int tid  = threadIdx.x;
    const int lane = tid & 31;
    const int warp = tid >> 5;
    const int tig  = lane & 3;
    const int gid  = lane >> 2;

    const uint32_t smem_base = (uint32_t)__cvta_generic_to_shared(smem);

    // --- weight smem fill via cp.async (pre-packed, coalesced) ---
    {
        const uint32_t dst0 = smem_base + OFF_W0F * 4;
        #pragma unroll
        for (int i = 0; i < 3; i++)
            cp_async16(dst0 + (tid + 256 * i) * 16, (const char*)g_w0f + (tid + 256 * i) * 16);
        cp_async16(smem_base + OFF_W1F * 4 + tid * 16, (const char*)g_w1f + tid * 16);
        asm volatile("cp.async.commit_group;");
    }

    // --- block -> (b, ty0, tx0) ---
    int bb = blockIdx.x;
    const int tx0 = (bb & 7) * TA_W;   bb >>= 3;     // IMG/TA_W = 8
    const int ty0 = (bb & 31) * TA_H;  bb >>= 5;     // IMG/TA_H = 32
    const int b = bb;
    const float* ximg = x + (size_t)b * IMG * IMG * CH;

    // --- halo fill: LDG float4 x4 -> half2 -> 2 STS.128 (one per plane) ---
    for (int p = tid; p < HA_PIX; p += TA_THREADS) {
        const int hy = ty0 + (p / HA_W) - 1;
        const int hx = tx0 + (p % HA_W) - 1;
        uint4 pl0 = make_uint4(0u, 0u, 0u, 0u);
        uint4 pl1 = make_uint4(0u, 0u, 0u, 0u);
        if ((unsigned)hy < IMG && (unsigned)hx < IMG) {
            const float4* src = (const float4*)(ximg + ((size_t)hy * IMG + hx) * CH);
            const float4 v0 = src[0], v1 = src[1], v2 = src[2], v3 = src[3];
            pl0 = make_uint4(pk2h(v0.x, v0.y), pk2h(v0.z, v0.w),
                             pk2h(v1.x, v1.y), pk2h(v1.z, v1.w));
            pl1 = make_uint4(pk2h(v2.x, v2.y), pk2h(v2.z, v2.w),
                             pk2h(v3.x, v3.y), pk2h(v3.z, v3.w));
        }
        *(uint4*)(sxh + p * 4) = pl0;
        *(uint4*)(sxh + PLSTRIDE + p * 4) = pl1;
    }
    asm volatile("cp.async.wait_group 0;");
    __syncthreads();

    // --- perceive: 1 thread = 1 pixel; half2 stencil, 9 taps x 2 planes ---
    {
        const int pty = tid >> 5, ptx = tid & 31;
        const int pcen = (pty + 1) * HA_W + (ptx + 1);

        uint32_t feat[24];   // words: id[0..7], sx[8..15], sy[16..23]
        #pragma unroll
        for (int q = 0; q < 2; q++) {
            const uint32_t* pl = sxh + q * PLSTRIDE;
            const uint4 t0 = *(const uint4*)(pl + (pcen - HA_W - 1) * 4);
            const uint4 t1 = *(const uint4*)(pl + (pcen - HA_W    ) * 4);
            const uint4 t2 = *(const uint4*)(pl + (pcen - HA_W + 1) * 4);
            const uint4 t3 = *(const uint4*)(pl + (pcen        - 1) * 4);
            const uint4 t4 = *(const uint4*)(pl + (pcen           ) * 4);
            const uint4 t5 = *(const uint4*)(pl + (pcen        + 1) * 4);
            const uint4 t6 = *(const uint4*)(pl + (pcen + HA_W - 1) * 4);
            const uint4 t7 = *(const uint4*)(pl + (pcen + HA_W    ) * 4);
            const uint4 t8 = *(const uint4*)(pl + (pcen + HA_W + 1) * 4);

            #define NCA_STEN(W, WI)                                            \
            {                                                                  \
                const int wi = q * 4 + (WI);                                   \
                feat[wi] = t4.W;                                               \
                const uint32_t sa = hsub2u(hadd2u(t2.W, t8.W),                 \
                                           hadd2u(t0.W, t6.W));                \
                const uint32_t sd = hsub2u(t5.W, t3.W);                        \
                feat[8 + wi] = hadd2u(sa, hadd2u(sd, sd));                     \
                const uint32_t ya = hsub2u(hadd2u(t6.W, t8.W),                 \
                                           hadd2u(t0.W, t2.W));                \
                const uint32_t yd = hsub2u(t7.W, t1.W);                        \
                feat[16 + wi] = hadd2u(ya, hadd2u(yd, yd));                    \
            }
            NCA_STEN(x, 0) NCA_STEN(y, 1) NCA_STEN(z, 2) NCA_STEN(w, 3)
            #undef NCA_STEN
        }

        // Y store with physw permutation baked in
        uint32_t* yrow = sY + tid * YSTRIDE;
        #pragma unroll
        for (int g = 0; g < 3; g++) {
            *(uint4*)(yrow + 8 * g)     = make_uint4(feat[8*g + 0], feat[8*g + 4],
                                                     feat[8*g + 1], feat[8*g + 5]);
            *(uint4*)(yrow + 8 * g + 4) = make_uint4(feat[8*g + 2], feat[8*g + 6],
                                                     feat[8*g + 3], feat[8*g + 7]);
        }
    }
    // Y rows consumed by this warp were written only by this warp's threads.
    __syncwarp();

    // --- prefetch rmask (4 pixels per thread: 2 tiles x 2 rows) ---
    const int gy = ty0 + warp;
    const size_t rowbase = ((size_t)b * IMG + gy) * IMG + tx0;
    float rmv[2][2];
    #pragma unroll
    for (int tt = 0; tt < 2; tt++)
        #pragma unroll
        for (int rr = 0; rr < 2; rr++)
            rmv[tt][rr] = rmask[rowbase + 16 * tt + gid + 8 * rr];

    // --- A-fragments for both m16 tiles ---
    uint32_t a1f[2][3][4];
    #pragma unroll
    for (int tt = 0; tt < 2; tt++) {
        const int rb = warp * 32 + 16 * tt;
        #pragma unroll
        for (int s = 0; s < 3; s++) {
            const uint2 lo = *(const uint2*)(sY + (rb + gid)     * YSTRIDE + 8 * s + 2 * tig);
            const uint2 hi = *(const uint2*)(sY + (rb + gid + 8) * YSTRIDE + 8 * s + 2 * tig);
            a1f[tt][s][0] = lo.x;  a1f[tt][s][1] = hi.x;
            a1f[tt][s][2] = lo.y;  a1f[tt][s][3] = hi.y;
        }
    }

    // --- fused GEMM1 -> relu/pack -> GEMM2, B-frags shared by both tiles ---
    float d[2][2][4];
    #pragma unroll
    for (int tt = 0; tt < 2; tt++)
        #pragma unroll
        for (int jj = 0; jj < 2; jj++)
            #pragma unroll
            for (int q = 0; q < 4; q++) d[tt][jj][q] = 0.0f;

    #pragma unroll
    for (int s2 = 0; s2 < 8; s2++) {
        float aA0[4] = {0.f,0.f,0.f,0.f}, aA1[4] = {0.f,0.f,0.f,0.f};
        float aB0[4] = {0.f,0.f,0.f,0.f}, aB1[4] = {0.f,0.f,0.f,0.f};
        #pragma unroll
        for (int s = 0; s < 3; s++) {
            const uint4 bb4 = ((const uint4*)w0f)[(s * 8 + s2) * 32 + lane];
            mma_f16(aA0, a1f[0][s][0], a1f[0][s][1], a1f[0][s][2], a1f[0][s][3], bb4.x, bb4.y);
            mma_f16(aA1, a1f[0][s][0], a1f[0][s][1], a1f[0][s][2], a1f[0][s][3], bb4.z, bb4.w);
            mma_f16(aB0, a1f[1][s][0], a1f[1][s][1], a1f[1][s][2], a1f[1][s][3], bb4.x, bb4.y);
            mma_f16(aB1, a1f[1][s][0], a1f[1][s][1], a1f[1][s][2], a1f[1][s][3], bb4.z, bb4.w);
        }
        const uint4 b2 = ((const uint4*)w1f)[s2 * 32 + lane];
        {
            const uint32_t f0 = pk2h(fmaxf(aA0[0], 0.f), fmaxf(aA0[1], 0.f));
            const uint32_t f1 = pk2h(fmaxf(aA0[2], 0.f), fmaxf(aA0[3], 0.f));
            const uint32_t f2 = pk2h(fmaxf(aA1[0], 0.f), fmaxf(aA1[1], 0.f));
            const uint32_t f3 = pk2h(fmaxf(aA1[2], 0.f), fmaxf(aA1[3], 0.f));
            mma_f16(d[0][0], f0, f1, f2, f3, b2.x, b2.y);
            mma_f16(d[0][1], f0, f1, f2, f3, b2.z, b2.w);
        }
        {
            const uint32_t f0 = pk2h(fmaxf(aB0[0], 0.f), fmaxf(aB0[1], 0.f));
            const uint32_t f1 = pk2h(fmaxf(aB0[2], 0.f), fmaxf(aB0[3], 0.f));
            const uint32_t f2 = pk2h(fmaxf(aB1[0], 0.f), fmaxf(aB1[1], 0.f));
            const uint32_t f3 = pk2h(fmaxf(aB1[2], 0.f), fmaxf(aB1[3], 0.f));
            mma_f16(d[1][0], f0, f1, f2, f3, b2.x, b2.y);
            mma_f16(d[1][1], f0, f1, f2, f3, b2.z, b2.w);
        }
    }

    // --- epilogue: x_new = x(gmem, fp32 exact) + dx*(rand<=0.5) -> OUT ---
    #pragma unroll
    for (int tt = 0; tt < 2; tt++) {
        #pragma unroll
        for (int rr = 0; rr < 2; rr++) {
            const int ptx = 16 * tt + gid + 8 * rr;
            const size_t pix = rowbase + ptx;
            const float upd = (rmv[tt][rr] <= 0.5f) ? 1.0f : 0.0f;
            #pragma unroll
            for (int jj = 0; jj < 2; jj++) {
                const int ch = 8 * jj + 2 * tig;
                const float2 xv = *(const float2*)(x + pix * CH + ch);
                float2 v;
                v.x = xv.x + d[tt][jj][2 * rr + 0] * upd;
                v.y = xv.y + d[tt][jj][2 * rr + 1] * upd;
                *(float2*)(out + pix * CH + ch) = v;
                if (jj == 0 && tig == 1) {       // ch pair (2,3): alpha = .y
                    g_aon[pix] = pk2bf(xv.y, v.y);   // (old, new) bf16x2
                }
            }
        }
    }
}

// --------------------- Pass B (fix-up, smem-free, shuffles) -----------------
// Warp = pixel row, lane = aligned pixel pair (cols 2*lane, 2*lane+1) within
// a 64-col strip. 3 coalesced LDG.64 build vertical maxes; side columns come
// from neighbor lanes via shuffles; strip-edge lanes load 3 extra words.
#define TB_THREADS 256   // 8 warps = 8 rows

__global__ __launch_bounds__(TB_THREADS)
void nca_pass_b(float* __restrict__ out)
{
    const int tid  = threadIdx.x;
    const int lane = tid & 31;
    const int wrp  = tid >> 5;

    int bb = blockIdx.x;
    const int tx0 = (bb & 3) * 64;  bb >>= 2;    // IMG/64 = 4 strips
    const int ty0 = (bb & 31) * 8;  bb >>= 5;    // IMG/8 = 32 row groups
    const int b = bb;
    const uint32_t* base = g_aon + (size_t)b * IMG * IMG;

    const int gy = ty0 + wrp;            // pixel row
    const int gx = tx0 + 2 * lane;       // first pixel col of this pair

    const __nv_bfloat162 z2 = __floats2bfloat162_rn(0.f, 0.f);
    __nv_bfloat162 vx = z2, vy = z2, ve = z2;

    // Edge column for strip boundary lanes: lane0 -> gx-1, lane31 -> gx+2.
    const int ecol = (lane == 0) ? (gx - 1) : (gx + 2);
    const bool eneed = (lane == 0 || lane == 31) && (unsigned)ecol < IMG;

    #pragma unroll
    for (int dr = -1; dr <= 1; dr++) {
        const int r = gy + dr;
        if ((unsigned)r < IMG) {
            const uint2 w = *(const uint2*)(base + (size_t)r * IMG + gx);
            vx = bmax2(vx, u2bf2(w.x));
            vy = bmax2(vy, u2bf2(w.y));
            if (eneed)
                ve = bmax2(ve, u2bf2(base[(size_t)r * IMG + ecol]));
        }
    }

    const unsigned fm = 0xffffffffu;
    const uint32_t vprevu = __shfl_up_sync(fm, bf22u(vy), 1);
    const uint32_t vnextu = __shfl_down_sync(fm, bf22u(vx), 1);
    const __nv_bfloat162 vprev = (lane == 0)  ? ve : u2bf2(vprevu);  // col gx-1
    const __nv_bfloat162 vnext = (lane == 31) ? ve : u2bf2(vnextu);  // col gx+2

    const __nv_bfloat162 common = bmax2(vx, vy);
    const __nv_bfloat162 m0 = bmax2(common, vprev);   // pixel gx
    const __nv_bfloat162 m1 = bmax2(common, vnext);   // pixel gx+1

    const size_t rowpix = (size_t)b * IMG * IMG + (size_t)gy * IMG + gx;
    const float4 z = make_float4(0.f, 0.f, 0.f, 0.f);

    if (!(__bfloat162float(m0.x) > 0.1f && __bfloat162float(m0.y) > 0.1f)) {
        float4* dst = (float4*)(out + rowpix * CH);
        dst[0] = z; dst[1] = z; dst[2] = z; dst[3] = z;
    }
    if (!(__bfloat162float(m1.x) > 0.1f && __bfloat162float(m1.y) > 0.1f)) {
        float4* dst = (float4*)(out + (rowpix + 1) * CH);
        dst[0] = z; dst[1] = z; dst[2] = z; dst[3] = z;
    }
}

// ----------------------------------------------------------------------------
extern "C" void kernel_launch(void* const* d_in, const int* in_sizes, int n_in,
                              void* d_out, int out_size)
{
    (void)in_sizes; (void)n_in; (void)out_size;
    const float* x  = (const float*)d_in[0];
    const float* w0 = (const float*)d_in[1];
    const float* w1 = (const float*)d_in[2];
    const float* rm = (const float*)d_in[3];
    float* out = (float*)d_out;

    cudaFuncSetAttribute(nca_pass_a, cudaFuncAttributeMaxDynamicSharedMemorySize,
                         SMEM_A_BYTES);

    const int grid_a = BATCH * (IMG / TA_H) * (IMG / TA_W); // 4096
    const int grid_b = BATCH * 32 * 4;                      // 2048

    nca_pack<<<12, 128>>>(w0, w1);
    nca_pass_a<<<grid_a, TA_THREADS, SMEM_A_BYTES>>>(x, rm, out);
    nca_pass_b<<<grid_b, TB_THREADS>>>(out);
}